// round 5
// baseline (speedup 1.0000x reference)
#include <cuda_runtime.h>
#include <cuda_fp16.h>

// Capsule routing, B=32, I=1024, O=64, D_in=16, D_out=32.
// R4: route reverts to low-reg form, G_=2 groups loaded UPFRONT (MLP=16,
//     ~96 regs). uhat threads own 2 od rows (wp[16], ~75 regs -> 3 blk/SM).

#define B_   32
#define I_   1024
#define O_   64
#define DN   16
#define DD   32
#define OD   2048      // O_*DD
#define CH   8         // capsules (i) per chunk
#define G_   2         // chunks per route block
#define NG   64        // I_/(CH*G_) partial groups
#define OD4  512

__device__ __half g_uhat[(size_t)B_ * I_ * OD];  // 134 MB (fp16)
__device__ float  g_part[(size_t)NG * B_ * OD];  // 16.8 MB group partials
__device__ float  g_bij [(size_t)B_ * I_ * O_];  // 8 MB routing logits
__device__ float  g_v   [(size_t)B_ * OD];       // v_j

#define FFMA2(d, a, b, c) \
    asm("fma.rn.f32x2 %0, %1, %2, %3;" : "=l"(d) : "l"(a), "l"(b), "l"(c))
#define MUL2(d, a, b) \
    asm("mul.rn.f32x2 %0, %1, %2;" : "=l"(d) : "l"(a), "l"(b))
#define PACK2(d, lo, hi) \
    asm("mov.b64 %0, {%1, %2};" : "=l"(d) : "f"(lo), "f"(hi))
#define UNPACK2(lo, hi, v) \
    asm("mov.b64 {%0, %1}, %2;" : "=f"(lo), "=f"(hi) : "l"(v))

// ---------------------------------------------------------------------------
// K1: u_hat (fp16). grid = (4 od-slices, 128 chunks), 256 threads.
// Thread owns 2 od rows; k paired into f32x2 lanes.
// ---------------------------------------------------------------------------
__global__ __launch_bounds__(256) void k_uhat(const float* __restrict__ x,
                                              const float* __restrict__ W) {
    __shared__ float xs[CH][B_][DN];   // 16 KB
    const int od0 = blockIdx.x * 512 + threadIdx.x * 2;
    const int i0  = blockIdx.y * CH;

    for (int j = threadIdx.x; j < CH * B_ * DN; j += 256) {
        int b  = j >> 7;
        int il = (j >> 4) & (CH - 1);
        int n  = j & (DN - 1);
        xs[il][b][n] = x[(size_t)b * (I_ * DN) + (i0 + il) * DN + n];
    }
    __syncthreads();

#pragma unroll 1
    for (int il = 0; il < CH; il++) {
        const int i = i0 + il;
        // W rows od0, od0+1 : 32 consecutive floats = 16 f32x2 pairs
        const float4* wr = reinterpret_cast<const float4*>(
            W + ((size_t)i * OD + od0) * DN);
        unsigned long long wp[16];          // [od][kpair] : od*8 + kp
#pragma unroll
        for (int r = 0; r < 8; r++) {
            const float4 f = wr[r];
            PACK2(wp[r * 2 + 0], f.x, f.y);
            PACK2(wp[r * 2 + 1], f.z, f.w);
        }
        __half* ubase = g_uhat + (size_t)i * OD + od0;

#pragma unroll 4
        for (int b = 0; b < B_; b++) {
            const float4* xb = reinterpret_cast<const float4*>(xs[il][b]);
            const float4 x0 = xb[0], x1 = xb[1], x2 = xb[2], x3 = xb[3];
            unsigned long long xp[8];
            PACK2(xp[0], x0.x, x0.y); PACK2(xp[1], x0.z, x0.w);
            PACK2(xp[2], x1.x, x1.y); PACK2(xp[3], x1.z, x1.w);
            PACK2(xp[4], x2.x, x2.y); PACK2(xp[5], x2.z, x2.w);
            PACK2(xp[6], x3.x, x3.y); PACK2(xp[7], x3.z, x3.w);

            unsigned long long acc0, acc1;
            MUL2(acc0, wp[0], xp[0]);
            MUL2(acc1, wp[8], xp[0]);
#pragma unroll
            for (int kp = 1; kp < 8; kp++) {
                FFMA2(acc0, wp[kp],     xp[kp], acc0);
                FFMA2(acc1, wp[8 + kp], xp[kp], acc1);
            }
            float l0, h0, l1, h1;
            UNPACK2(l0, h0, acc0);
            UNPACK2(l1, h1, acc1);
            const __half2 hh = __floats2half2_rn(l0 + h0, l1 + h1);
            *reinterpret_cast<__half2*>(ubase + (size_t)b * (I_ * OD)) = hh;
        }
    }
}

// ---------------------------------------------------------------------------
// K1b: s0 partials = unweighted i-sums of u_hat (softmax(0) is uniform).
// grid = (NG, 32), 256 threads; thread owns 8 ods, sums CH*G_ i's.
// ---------------------------------------------------------------------------
__global__ __launch_bounds__(256) void k_sum0() {
    const int b = blockIdx.y;
    const int i0 = blockIdx.x * (CH * G_);
    const uint4* src = reinterpret_cast<const uint4*>(
        g_uhat + ((size_t)b * I_ + i0) * OD) + threadIdx.x;

    float4 r0 = {0,0,0,0}, r1 = {0,0,0,0};
#pragma unroll
    for (int il = 0; il < CH * G_; il++) {
        const uint4 u = src[il * 256];
        const __half2* h = reinterpret_cast<const __half2*>(&u);
        const float2 f0 = __half22float2(h[0]), f1 = __half22float2(h[1]);
        const float2 f2 = __half22float2(h[2]), f3 = __half22float2(h[3]);
        r0.x += f0.x; r0.y += f0.y; r0.z += f1.x; r0.w += f1.y;
        r1.x += f2.x; r1.y += f2.y; r1.z += f3.x; r1.w += f3.y;
    }
    float4* gp = reinterpret_cast<float4*>(
        g_part + ((size_t)blockIdx.x * B_ + b) * OD) + threadIdx.x * 2;
    gp[0] = r0;
    gp[1] = r1;
}

// ---------------------------------------------------------------------------
// K2: group-reduce + squash. grid = (4, 32), 128 threads.
// ---------------------------------------------------------------------------
__global__ __launch_bounds__(128) void k_squash(float factor,
                                                const float* __restrict__ bias,
                                                float* __restrict__ out) {
    const int b    = blockIdx.y;
    const int w    = threadIdx.x >> 5;
    const int lane = threadIdx.x & 31;
    const int o    = blockIdx.x * 16 + w * 4 + (lane >> 3);
    const int dg   = lane & 7;

    const float4* gp = reinterpret_cast<const float4*>(g_part);
    const size_t base = (size_t)b * OD4 + o * 8 + dg;

    float4 a0 = {0,0,0,0}, a1 = {0,0,0,0}, a2 = {0,0,0,0}, a3 = {0,0,0,0};
#pragma unroll
    for (int t = 0; t < NG; t += 4) {
        float4 p0 = gp[(size_t)(t + 0) * B_ * OD4 + base];
        float4 p1 = gp[(size_t)(t + 1) * B_ * OD4 + base];
        float4 p2 = gp[(size_t)(t + 2) * B_ * OD4 + base];
        float4 p3 = gp[(size_t)(t + 3) * B_ * OD4 + base];
        a0.x += p0.x; a0.y += p0.y; a0.z += p0.z; a0.w += p0.w;
        a1.x += p1.x; a1.y += p1.y; a1.z += p1.z; a1.w += p1.w;
        a2.x += p2.x; a2.y += p2.y; a2.z += p2.z; a2.w += p2.w;
        a3.x += p3.x; a3.y += p3.y; a3.z += p3.z; a3.w += p3.w;
    }
    float4 s;
    s.x = (a0.x + a1.x + a2.x + a3.x) * factor;
    s.y = (a0.y + a1.y + a2.y + a3.y) * factor;
    s.z = (a0.z + a1.z + a2.z + a3.z) * factor;
    s.w = (a0.w + a1.w + a2.w + a3.w) * factor;
    if (bias) {
        const float4 bb = reinterpret_cast<const float4*>(bias)[o * 8 + dg];
        s.x += bb.x; s.y += bb.y; s.z += bb.z; s.w += bb.w;
    }

    float q = s.x * s.x + s.y * s.y + s.z * s.z + s.w * s.w;
    q += __shfl_xor_sync(0xffffffffu, q, 1);
    q += __shfl_xor_sync(0xffffffffu, q, 2);
    q += __shfl_xor_sync(0xffffffffu, q, 4);

    const float scale = q / (1.f + q) * rsqrtf(q + 1e-8f);
    s.x *= scale; s.y *= scale; s.z *= scale; s.w *= scale;
    float4* dst = reinterpret_cast<float4*>(out ? out : g_v);
    dst[(size_t)b * OD4 + o * 8 + dg] = s;
}

// ---------------------------------------------------------------------------
// K3: one routing pass, register-resident. grid = (NG, 32), 256 threads.
// Both G_=2 chunk groups loaded upfront: 16 independent LDG.128 (MLP=16).
// ---------------------------------------------------------------------------
__global__ __launch_bounds__(256) void k_route(int use_bij_in, int write_bij) {
    __shared__ float sa[CH][O_];
    __shared__ float sc[CH][O_];

    const int b  = blockIdx.y;
    const int t  = threadIdx.x;
    const int o  = t >> 2;
    const int ibase = blockIdx.x * (CH * G_);

    const uint4* usrc = reinterpret_cast<const uint4*>(
        g_uhat + ((size_t)b * I_ + ibase) * OD) + t;

    uint4 u[G_][CH];
#pragma unroll
    for (int g = 0; g < G_; g++)
#pragma unroll
        for (int il = 0; il < CH; il++)
            u[g][il] = usrc[(g * CH + il) * 256];

    const float4* vsrc =
        reinterpret_cast<const float4*>(g_v + (size_t)b * OD) + t * 2;
    const float4 v0 = vsrc[0], v1 = vsrc[1];

    float4 r0 = {0,0,0,0}, r1 = {0,0,0,0};

#pragma unroll
    for (int g = 0; g < G_; g++) {
        const int i0 = ibase + g * CH;

        // agreement: quad-reduced dot with v
#pragma unroll
        for (int il = 0; il < CH; il++) {
            const __half2* h = reinterpret_cast<const __half2*>(&u[g][il]);
            const float2 f0 = __half22float2(h[0]), f1 = __half22float2(h[1]);
            const float2 f2 = __half22float2(h[2]), f3 = __half22float2(h[3]);
            float a;
            a  = f0.x * v0.x;         a = fmaf(f0.y, v0.y, a);
            a  = fmaf(f1.x, v0.z, a); a = fmaf(f1.y, v0.w, a);
            a  = fmaf(f2.x, v1.x, a); a = fmaf(f2.y, v1.y, a);
            a  = fmaf(f3.x, v1.z, a); a = fmaf(f3.y, v1.w, a);
            a += __shfl_xor_sync(0xffffffffu, a, 1);
            a += __shfl_xor_sync(0xffffffffu, a, 2);
            if ((t & 3) == 0) sa[il][o] = a;
        }
        __syncthreads();

        // softmax over O: warp wid -> capsule wid
        {
            const int wid  = t >> 5;
            const int lane = t & 31;
            const int i = i0 + wid;
            float a0 = sa[wid][lane];
            float a1 = sa[wid][lane + 32];
            if (use_bij_in) {
                a0 += g_bij[((size_t)b * I_ + i) * O_ + lane];
                a1 += g_bij[((size_t)b * I_ + i) * O_ + lane + 32];
            }
            if (write_bij) {
                g_bij[((size_t)b * I_ + i) * O_ + lane]      = a0;
                g_bij[((size_t)b * I_ + i) * O_ + lane + 32] = a1;
            }
            float m = fmaxf(a0, a1);
#pragma unroll
            for (int s = 16; s > 0; s >>= 1)
                m = fmaxf(m, __shfl_xor_sync(0xffffffffu, m, s));
            const float e0 = __expf(a0 - m);
            const float e1 = __expf(a1 - m);
            float es = e0 + e1;
#pragma unroll
            for (int s = 16; s > 0; s >>= 1)
                es += __shfl_xor_sync(0xffffffffu, es, s);
            const float inv = 1.f / es;
            sc[wid][lane]      = e0 * inv;
            sc[wid][lane + 32] = e1 * inv;
        }
        __syncthreads();

        // weighted sum accumulate
#pragma unroll
        for (int il = 0; il < CH; il++) {
            const float s = sc[il][o];
            const __half2* h = reinterpret_cast<const __half2*>(&u[g][il]);
            const float2 f0 = __half22float2(h[0]), f1 = __half22float2(h[1]);
            const float2 f2 = __half22float2(h[2]), f3 = __half22float2(h[3]);
            r0.x = fmaf(s, f0.x, r0.x); r0.y = fmaf(s, f0.y, r0.y);
            r0.z = fmaf(s, f1.x, r0.z); r0.w = fmaf(s, f1.y, r0.w);
            r1.x = fmaf(s, f2.x, r1.x); r1.y = fmaf(s, f2.y, r1.y);
            r1.z = fmaf(s, f3.x, r1.z); r1.w = fmaf(s, f3.y, r1.w);
        }
    }

    float4* gp = reinterpret_cast<float4*>(
        g_part + ((size_t)blockIdx.x * B_ + b) * OD) + t * 2;
    gp[0] = r0;
    gp[1] = r1;
}

// ---------------------------------------------------------------------------
extern "C" void kernel_launch(void* const* d_in, const int* in_sizes, int n_in,
                              void* d_out, int out_size) {
    const float* x    = (const float*)d_in[0];   // [32,1024,16]
    const float* W    = (const float*)d_in[1];   // [1,1024,64,32,16]
    const float* bias = (const float*)d_in[2];   // [1,1,64,32]
    float* out = (float*)d_out;                  // [32,64,32]

    k_uhat<<<dim3(4, 128), 256>>>(x, W);                             // 1
    k_sum0<<<dim3(NG, B_), 256>>>();                                 // 2
    k_squash<<<dim3(4, 32), 128>>>(1.0f / 64.0f, nullptr, nullptr);  // 3: v0
    k_route<<<dim3(NG, B_), 256>>>(0, 1);                            // 4
    k_squash<<<dim3(4, 32), 128>>>(1.0f, nullptr, nullptr);          // 5: v1
    k_route<<<dim3(NG, B_), 256>>>(1, 0);                            // 6 (ncu)
    k_squash<<<dim3(4, 32), 128>>>(1.0f, bias, out);                 // 7: out
}